// round 12
// baseline (speedup 1.0000x reference)
#include <cuda_runtime.h>

#define T_LEN 4995
#define BATCH 64
#define VOCAB 4096
#define EDIM  100
#define UDIM  64
#define G3    192    // 3*U gate width
#define GPAD  256    // padded gate row: [64 cols][4] (z,r,h,pad)
#define NTHR  384
#define KSLOT 1251   // slots of 4 timesteps

// Precomputed (emb @ W1 + b1[0]) table, packed [VOCAB][64][4] = (z,r,h,0)
__device__ __align__(16) float g_tab[VOCAB * GPAD];

__device__ __forceinline__ void ffma2(float2& acc, const float2 a, const float2 b) {
    asm("fma.rn.f32x2 %0, %1, %2, %0;"
        : "+l"(reinterpret_cast<unsigned long long&>(acc))
        : "l"(*reinterpret_cast<const unsigned long long*>(&a)),
          "l"(*reinterpret_cast<const unsigned long long*>(&b)));
}
__device__ __forceinline__ float2 fadd2(const float2 a, const float2 b) {
    float2 r;
    asm("add.rn.f32x2 %0, %1, %2;"
        : "=l"(reinterpret_cast<unsigned long long&>(r))
        : "l"(*reinterpret_cast<const unsigned long long*>(&a)),
          "l"(*reinterpret_cast<const unsigned long long*>(&b)));
    return r;
}

__device__ __forceinline__ float tanha(float x) {
    float y; asm("tanh.approx.f32 %0, %1;" : "=f"(y) : "f"(x)); return y;
}
__device__ __forceinline__ float sigf(float x) {
    return fmaf(tanha(0.5f * x), 0.5f, 0.5f);    // 0.5*tanh(x/2)+0.5
}

// Pair-split 3-gate dot: each lane does a half-dot (32 k) for 3 gates,
// h loaded as 8x LDS.128, combine with partner lane via shfl.xor 1.
__device__ __forceinline__ void dot3(const float4* __restrict__ hv4,
                                     const float2 w[3][16],
                                     float bz, float br, float bh,
                                     float& s0, float& s1, float& s2) {
    float2 h[16];
#pragma unroll
    for (int m = 0; m < 8; m++) {
        const float4 v = hv4[m];
        h[2 * m]     = make_float2(v.x, v.y);
        h[2 * m + 1] = make_float2(v.z, v.w);
    }
    float2 a0 = {bz, 0.f}, a1 = {0.f, 0.f};
    float2 r0 = {br, 0.f}, r1 = {0.f, 0.f};
    float2 c0 = {bh, 0.f}, c1 = {0.f, 0.f};
#pragma unroll
    for (int m = 0; m < 16; m += 2) {
        ffma2(a0, h[m], w[0][m]); ffma2(a1, h[m + 1], w[0][m + 1]);
        ffma2(r0, h[m], w[1][m]); ffma2(r1, h[m + 1], w[1][m + 1]);
        ffma2(c0, h[m], w[2][m]); ffma2(c1, h[m + 1], w[2][m + 1]);
    }
    const float2 sa = fadd2(a0, a1), sr = fadd2(r0, r1), sc = fadd2(c0, c1);
    s0 = sa.x + sa.y;
    s1 = sr.x + sr.y;
    s2 = sc.x + sc.y;
    s0 += __shfl_xor_sync(0xFFFFFFFFu, s0, 1);
    s1 += __shfl_xor_sync(0xFFFFFFFFu, s1, 1);
    s2 += __shfl_xor_sync(0xFFFFFFFFu, s2, 1);
}

// ---------------------------------------------------------------------------
// Kernel 1: g_tab[v][col][g] = sum_e emb[v][e]*W1[e][g*64+col] + b1[0][g*64+col]
// ---------------------------------------------------------------------------
__global__ void build_tab(const float* __restrict__ emb,
                          const float* __restrict__ W1,
                          const float* __restrict__ b1) {
    __shared__ float es[EDIM];
    const int v = blockIdx.x;
    const int j = threadIdx.x;          // 0..191, gate column g*64+col
    for (int e = j; e < EDIM; e += G3) es[e] = emb[v * EDIM + e];
    __syncthreads();
    float s = b1[j];
#pragma unroll 4
    for (int e = 0; e < EDIM; e++) s += es[e] * __ldg(&W1[e * G3 + j]);
    const int col = j & 63, g = j >> 6;
    g_tab[v * GPAD + col * 4 + g] = s;
    if (j < 64) g_tab[v * GPAD + j * 4 + 3] = 0.0f;
}

// ---------------------------------------------------------------------------
// Kernel 2: fused 2-layer GRU, skewed pipeline, 4 timesteps per slot.
// NO CTA-wide barrier in the loop: pairwise named barriers only.
//   role A (tid   0..127): h1[4k .. 4k+3]   (3x bar.sync 1,128) ... bar.sync 3,256
//   role C (tid 128..255): cp.async xt[4k+12..4k+15]; x2[4k-4..4k-1];
//                          bar.sync 3,256 ; bar.sync 4,256
//   role B (tid 256..383): h2[4k-8 .. 4k-5] (3x bar.sync 2,128) ... bar.sync 4,256
// Rings: h1/h2/x2 mod 8, xt mod 16 (prefetch distance 3 slots = 12 steps).
// A<->B never synchronize inside the loop (no shared data).
// ---------------------------------------------------------------------------
__global__ void __launch_bounds__(NTHR, 1)
gru_fused(const int*   __restrict__ tokens,
          const float* __restrict__ U1w,
          const float* __restrict__ b1,
          const float* __restrict__ W2w,
          const float* __restrict__ U2w,
          const float* __restrict__ b2,
          const float* __restrict__ Wout,
          const float* __restrict__ bout,
          float*       __restrict__ out) {
    __shared__ int   toks[T_LEN];
    __shared__ __align__(16) float h1s[8][UDIM];
    __shared__ __align__(16) float h2s[8][UDIM];
    __shared__ __align__(16) float x2s[8][GPAD];   // [col][4] = (z,r,h,pad)
    __shared__ __align__(16) float xtr[16][GPAD];  // [col][4] = (z,r,h,pad)
    __shared__ __align__(16) float red[UDIM];

    const int tid = threadIdx.x;
    const int b   = blockIdx.x;

    if (tid < UDIM) {
        h1s[7][tid] = 0.0f;   // h1[-1]
        h2s[7][tid] = 0.0f;   // h2[-1]
    }
    for (int i = tid; i < T_LEN; i += NTHR)
        toks[i] = tokens[(long long)b * T_LEN + i];
    __syncthreads();
    // Preload xt for steps 0..11 (first 3 slots)
    for (int i = tid; i < 12 * GPAD; i += NTHR)
        xtr[i >> 8][i & 255] = g_tab[toks[i >> 8] * GPAD + (i & 255)];
    __syncthreads();

    const int role = tid >> 7;        // 0: A(layer1), 1: C(x2+prefetch), 2: B(layer2)
    const int t2   = tid & 127;
    const int col  = t2 >> 1;         // 0..63
    const int half = t2 & 1;

    // ---- per-thread register weights: half-dot (32 k-values) x 3 gates ----
    const float* Wm = (role == 0) ? U1w : (role == 1) ? W2w : U2w;
    float2 w[3][16];
#pragma unroll
    for (int g = 0; g < 3; g++)
#pragma unroll
        for (int m = 0; m < 16; m++) {
            const int k = half * 32 + 2 * m;
            w[g][m] = make_float2(Wm[k * G3 + g * 64 + col],
                                  Wm[(k + 1) * G3 + g * 64 + col]);
        }
    float bias[3];
#pragma unroll
    for (int g = 0; g < 3; g++) {
        float bv;
        if (role == 0)      bv = b1[G3 + g * 64 + col];   // recurrent bias L1
        else if (role == 1) bv = b2[g * 64 + col];        // input bias L2
        else                bv = b2[G3 + g * 64 + col];   // recurrent bias L2
        bias[g] = (half == 0) ? bv : 0.0f;
    }

    for (int k = 0; k < KSLOT; k++) {
        if (role == 0) {
            // ---------------- layer-1: steps 4k .. 4k+3 ----------------
#pragma unroll
            for (int sub = 0; sub < 4; sub++) {
                const int s = 4 * k + sub;
                if (s < T_LEN) {
                    const float4* hv4 = (const float4*)(h1s[(s - 1) & 7]) + half * 8;
                    const float4 xv = *((const float4*)&xtr[s & 15][col * 4]);
                    float az, ar, ah;
                    dot3(hv4, w, bias[0], bias[1], bias[2], az, ar, ah);
                    const float z  = sigf(xv.x + az);
                    const float r  = sigf(xv.y + ar);
                    const float hh = tanha(fmaf(r, ah, xv.z));
                    const float hold = h1s[(s - 1) & 7][col];
                    if (half == 0)
                        h1s[s & 7][col] = fmaf(z, hold - hh, hh);
                }
                if (sub < 3)
                    asm volatile("bar.sync 1, 128;" ::: "memory");
            }
            asm volatile("bar.sync 3, 256;" ::: "memory");   // A <-> C
        } else if (role == 1) {
            // ---- async prefetch xt for steps 4k+12..4k+15 (256 x 16B) ----
#pragma unroll
            for (int cc = 0; cc < 2; cc++) {
                const int c  = t2 + cc * 128;
                const int tp = 4 * k + 12 + (c >> 6);
                if (tp < T_LEN) {
                    const int tok = toks[tp];
                    const float* src = g_tab + tok * GPAD + (c & 63) * 4;
                    unsigned dst = (unsigned)__cvta_generic_to_shared(
                        &xtr[tp & 15][(c & 63) * 4]);
                    asm volatile("cp.async.cg.shared.global [%0], [%1], 16;"
                                 :: "r"(dst), "l"(src) : "memory");
                }
            }
            asm volatile("cp.async.commit_group;" ::: "memory");
            // -------- x2[4k-4 .. 4k-1]: independent, full ILP -------------
#pragma unroll
            for (int sub = 0; sub < 4; sub++) {
                const int s = 4 * k - 4 + sub;
                if (s >= 0 && s < T_LEN) {
                    const float4* hv4 = (const float4*)(h1s[s & 7]) + half * 8;
                    float sz, sr, sh;
                    dot3(hv4, w, bias[0], bias[1], bias[2], sz, sr, sh);
                    if (half == 0) {
                        float4* dst = (float4*)&x2s[s & 7][col * 4];
                        *dst = make_float4(sz, sr, sh, 0.0f);
                    }
                }
            }
            asm volatile("cp.async.wait_group 2;" ::: "memory");
            asm volatile("bar.sync 3, 256;" ::: "memory");   // A <-> C
            asm volatile("bar.sync 4, 256;" ::: "memory");   // C <-> B
        } else {
            // ---------------- layer-2: steps 4k-8 .. 4k-5 ----------------
#pragma unroll
            for (int sub = 0; sub < 4; sub++) {
                const int s = 4 * k - 8 + sub;
                if (s >= 0 && s < T_LEN) {
                    const float4* hv4 = (const float4*)(h2s[(s - 1) & 7]) + half * 8;
                    const float4 xv = *((const float4*)&x2s[s & 7][col * 4]);
                    float az, ar, ah;
                    dot3(hv4, w, bias[0], bias[1], bias[2], az, ar, ah);
                    const float z  = sigf(xv.x + az);
                    const float r  = sigf(xv.y + ar);
                    const float hh = tanha(fmaf(r, ah, xv.z));
                    const float hold = h2s[(s - 1) & 7][col];
                    if (half == 0)
                        h2s[s & 7][col] = fmaf(z, hold - hh, hh);
                }
                if (sub < 3)
                    asm volatile("bar.sync 2, 128;" ::: "memory");
            }
            asm volatile("bar.sync 4, 256;" ::: "memory");   // C <-> B
        }
    }

    // ---------------- Epilogue: sigmoid(h2[T-1] @ Wout + bout) ----------------
    __syncthreads();
    if (tid < UDIM) red[tid] = h2s[(T_LEN - 1) & 7][tid] * Wout[tid];
    __syncthreads();
    if (tid == 0) {
        float s = bout[0];
#pragma unroll
        for (int k = 0; k < UDIM; k++) s += red[k];
        out[b] = 1.0f / (1.0f + __expf(-s));
    }
}

// ---------------------------------------------------------------------------
extern "C" void kernel_launch(void* const* d_in, const int* in_sizes, int n_in,
                              void* d_out, int out_size) {
    const int*   tokens = (const int*)  d_in[0];
    const float* emb    = (const float*)d_in[1];
    const float* W1     = (const float*)d_in[2];
    const float* U1     = (const float*)d_in[3];
    const float* b1     = (const float*)d_in[4];
    const float* W2     = (const float*)d_in[5];
    const float* U2     = (const float*)d_in[6];
    const float* b2     = (const float*)d_in[7];
    const float* Wout   = (const float*)d_in[8];
    const float* bout   = (const float*)d_in[9];

    build_tab<<<VOCAB, G3>>>(emb, W1, b1);
    gru_fused<<<BATCH, NTHR>>>(tokens, U1, b1, W2, U2, b2, Wout, bout,
                               (float*)d_out);
}

// round 14
// speedup vs baseline: 1.6272x; 1.6272x over previous
#include <cuda_runtime.h>

#define T_LEN 4995
#define BATCH 64
#define VOCAB 4096
#define EDIM  100
#define UDIM  64
#define G3    192    // 3*U gate width
#define GPAD  256    // padded gate row: [64 cols][4] (z,r,h,pad)
#define NTHR  384
#define KSLOT 1251   // slots of 4 timesteps

// Precomputed (emb @ W1 + b1[0]) table, packed [VOCAB][64][4] = (z,r,h,0)
__device__ __align__(16) float g_tab[VOCAB * GPAD];

__device__ __forceinline__ void ffma2(float2& acc, const float2 a, const float2 b) {
    asm("fma.rn.f32x2 %0, %1, %2, %0;"
        : "+l"(reinterpret_cast<unsigned long long&>(acc))
        : "l"(*reinterpret_cast<const unsigned long long*>(&a)),
          "l"(*reinterpret_cast<const unsigned long long*>(&b)));
}
__device__ __forceinline__ float2 fadd2(const float2 a, const float2 b) {
    float2 r;
    asm("add.rn.f32x2 %0, %1, %2;"
        : "=l"(reinterpret_cast<unsigned long long&>(r))
        : "l"(*reinterpret_cast<const unsigned long long*>(&a)),
          "l"(*reinterpret_cast<const unsigned long long*>(&b)));
    return r;
}

__device__ __forceinline__ float tanha(float x) {
    float y; asm("tanh.approx.f32 %0, %1;" : "=f"(y) : "f"(x)); return y;
}
__device__ __forceinline__ float sigf(float x) {
    return fmaf(tanha(0.5f * x), 0.5f, 0.5f);    // 0.5*tanh(x/2)+0.5
}

// Pair-split 3-gate dot: each lane does a half-dot (32 k) for 3 gates,
// h loaded as 8x LDS.128, combine with partner lane via shfl.xor 1.
__device__ __forceinline__ void dot3(const float4* __restrict__ hv4,
                                     const float2 w[3][16],
                                     float bz, float br, float bh,
                                     float& s0, float& s1, float& s2) {
    float2 h[16];
#pragma unroll
    for (int m = 0; m < 8; m++) {
        const float4 v = hv4[m];
        h[2 * m]     = make_float2(v.x, v.y);
        h[2 * m + 1] = make_float2(v.z, v.w);
    }
    float2 a0 = {bz, 0.f}, a1 = {0.f, 0.f};
    float2 r0 = {br, 0.f}, r1 = {0.f, 0.f};
    float2 c0 = {bh, 0.f}, c1 = {0.f, 0.f};
#pragma unroll
    for (int m = 0; m < 16; m += 2) {
        ffma2(a0, h[m], w[0][m]); ffma2(a1, h[m + 1], w[0][m + 1]);
        ffma2(r0, h[m], w[1][m]); ffma2(r1, h[m + 1], w[1][m + 1]);
        ffma2(c0, h[m], w[2][m]); ffma2(c1, h[m + 1], w[2][m + 1]);
    }
    const float2 sa = fadd2(a0, a1), sr = fadd2(r0, r1), sc = fadd2(c0, c1);
    s0 = sa.x + sa.y;
    s1 = sr.x + sr.y;
    s2 = sc.x + sc.y;
    s0 += __shfl_xor_sync(0xFFFFFFFFu, s0, 1);
    s1 += __shfl_xor_sync(0xFFFFFFFFu, s1, 1);
    s2 += __shfl_xor_sync(0xFFFFFFFFu, s2, 1);
}

// ---------------------------------------------------------------------------
// Kernel 1: g_tab[v][col][g] = sum_e emb[v][e]*W1[e][g*64+col] + b1[0][g*64+col]
// ---------------------------------------------------------------------------
__global__ void build_tab(const float* __restrict__ emb,
                          const float* __restrict__ W1,
                          const float* __restrict__ b1) {
    __shared__ float es[EDIM];
    const int v = blockIdx.x;
    const int j = threadIdx.x;          // 0..191, gate column g*64+col
    for (int e = j; e < EDIM; e += G3) es[e] = emb[v * EDIM + e];
    __syncthreads();
    float s = b1[j];
#pragma unroll 4
    for (int e = 0; e < EDIM; e++) s += es[e] * __ldg(&W1[e * G3 + j]);
    const int col = j & 63, g = j >> 6;
    g_tab[v * GPAD + col * 4 + g] = s;
    if (j < 64) g_tab[v * GPAD + j * 4 + 3] = 0.0f;
}

// ---------------------------------------------------------------------------
// Kernel 2: fused 2-layer GRU, skewed pipeline, 4 timesteps per CTA barrier.
// (r11 champion structure; only gate I/O packed as float4.)
//
// Slot k (one __syncthreads; named bars inside A and B between sub-steps):
//   role A (tid   0..127): h1[4k .. 4k+3]           (3x bar.sync 1,128)
//   role C (tid 128..255): cp.async xt[4k+12..4k+15]; x2[4k-4 .. 4k-1] (indep)
//   role B (tid 256..383): h2[4k-8 .. 4k-5]          (3x bar.sync 2,128)
// Rings: h1/h2/x2 mod 8, xt mod 16 (prefetch distance 3 slots = 12 steps).
// ---------------------------------------------------------------------------
__global__ void __launch_bounds__(NTHR, 1)
gru_fused(const int*   __restrict__ tokens,
          const float* __restrict__ U1w,
          const float* __restrict__ b1,
          const float* __restrict__ W2w,
          const float* __restrict__ U2w,
          const float* __restrict__ b2,
          const float* __restrict__ Wout,
          const float* __restrict__ bout,
          float*       __restrict__ out) {
    __shared__ int   toks[T_LEN];
    __shared__ __align__(16) float h1s[8][UDIM];
    __shared__ __align__(16) float h2s[8][UDIM];
    __shared__ __align__(16) float x2s[8][GPAD];   // [col][4] = (z,r,h,pad)
    __shared__ __align__(16) float xtr[16][GPAD];  // [col][4] = (z,r,h,pad)
    __shared__ __align__(16) float red[UDIM];

    const int tid = threadIdx.x;
    const int b   = blockIdx.x;

    if (tid < UDIM) {
        h1s[7][tid] = 0.0f;   // h1[-1]
        h2s[7][tid] = 0.0f;   // h2[-1]
    }
    for (int i = tid; i < T_LEN; i += NTHR)
        toks[i] = tokens[(long long)b * T_LEN + i];
    __syncthreads();
    // Preload xt for steps 0..11 (first 3 slots)
    for (int i = tid; i < 12 * GPAD; i += NTHR)
        xtr[i >> 8][i & 255] = g_tab[toks[i >> 8] * GPAD + (i & 255)];
    __syncthreads();

    const int role = tid >> 7;        // 0: A(layer1), 1: C(x2+prefetch), 2: B(layer2)
    const int t2   = tid & 127;
    const int col  = t2 >> 1;         // 0..63
    const int half = t2 & 1;

    // ---- per-thread register weights: half-dot (32 k-values) x 3 gates ----
    const float* Wm = (role == 0) ? U1w : (role == 1) ? W2w : U2w;
    float2 w[3][16];
#pragma unroll
    for (int g = 0; g < 3; g++)
#pragma unroll
        for (int m = 0; m < 16; m++) {
            const int k = half * 32 + 2 * m;
            w[g][m] = make_float2(Wm[k * G3 + g * 64 + col],
                                  Wm[(k + 1) * G3 + g * 64 + col]);
        }
    float bias[3];
#pragma unroll
    for (int g = 0; g < 3; g++) {
        float bv;
        if (role == 0)      bv = b1[G3 + g * 64 + col];   // recurrent bias L1
        else if (role == 1) bv = b2[g * 64 + col];        // input bias L2
        else                bv = b2[G3 + g * 64 + col];   // recurrent bias L2
        bias[g] = (half == 0) ? bv : 0.0f;
    }

    for (int k = 0; k < KSLOT; k++) {
        if (role == 0) {
            // ---------------- layer-1: steps 4k .. 4k+3 ----------------
#pragma unroll
            for (int sub = 0; sub < 4; sub++) {
                const int s = 4 * k + sub;
                if (s < T_LEN) {
                    const float4* hv4 = (const float4*)(h1s[(s - 1) & 7]) + half * 8;
                    const float4 xv = *((const float4*)&xtr[s & 15][col * 4]);
                    float az, ar, ah;
                    dot3(hv4, w, bias[0], bias[1], bias[2], az, ar, ah);
                    const float z  = sigf(xv.x + az);
                    const float r  = sigf(xv.y + ar);
                    const float hh = tanha(fmaf(r, ah, xv.z));
                    const float hold = h1s[(s - 1) & 7][col];
                    if (half == 0)
                        h1s[s & 7][col] = fmaf(z, hold - hh, hh);
                }
                if (sub < 3)
                    asm volatile("bar.sync 1, 128;" ::: "memory");
            }
        } else if (role == 1) {
            // ---- async prefetch xt for steps 4k+12..4k+15 (256 x 16B) ----
#pragma unroll
            for (int cc = 0; cc < 2; cc++) {
                const int c  = t2 + cc * 128;
                const int tp = 4 * k + 12 + (c >> 6);
                if (tp < T_LEN) {
                    const int tok = toks[tp];
                    const float* src = g_tab + tok * GPAD + (c & 63) * 4;
                    unsigned dst = (unsigned)__cvta_generic_to_shared(
                        &xtr[tp & 15][(c & 63) * 4]);
                    asm volatile("cp.async.cg.shared.global [%0], [%1], 16;"
                                 :: "r"(dst), "l"(src) : "memory");
                }
            }
            asm volatile("cp.async.commit_group;" ::: "memory");
            // -------- x2[4k-4 .. 4k-1]: independent, full ILP -------------
#pragma unroll
            for (int sub = 0; sub < 4; sub++) {
                const int s = 4 * k - 4 + sub;
                if (s >= 0 && s < T_LEN) {
                    const float4* hv4 = (const float4*)(h1s[s & 7]) + half * 8;
                    float sz, sr, sh;
                    dot3(hv4, w, bias[0], bias[1], bias[2], sz, sr, sh);
                    if (half == 0) {
                        float4* dst = (float4*)&x2s[s & 7][col * 4];
                        *dst = make_float4(sz, sr, sh, 0.0f);
                    }
                }
            }
            asm volatile("cp.async.wait_group 2;" ::: "memory");
        } else {
            // ---------------- layer-2: steps 4k-8 .. 4k-5 ----------------
#pragma unroll
            for (int sub = 0; sub < 4; sub++) {
                const int s = 4 * k - 8 + sub;
                if (s >= 0 && s < T_LEN) {
                    const float4* hv4 = (const float4*)(h2s[(s - 1) & 7]) + half * 8;
                    const float4 xv = *((const float4*)&x2s[s & 7][col * 4]);
                    float az, ar, ah;
                    dot3(hv4, w, bias[0], bias[1], bias[2], az, ar, ah);
                    const float z  = sigf(xv.x + az);
                    const float r  = sigf(xv.y + ar);
                    const float hh = tanha(fmaf(r, ah, xv.z));
                    const float hold = h2s[(s - 1) & 7][col];
                    if (half == 0)
                        h2s[s & 7][col] = fmaf(z, hold - hh, hh);
                }
                if (sub < 3)
                    asm volatile("bar.sync 2, 128;" ::: "memory");
            }
        }
        __syncthreads();
    }

    // ---------------- Epilogue: sigmoid(h2[T-1] @ Wout + bout) ----------------
    if (tid < UDIM) red[tid] = h2s[(T_LEN - 1) & 7][tid] * Wout[tid];
    __syncthreads();
    if (tid == 0) {
        float s = bout[0];
#pragma unroll
        for (int k = 0; k < UDIM; k++) s += red[k];
        out[b] = 1.0f / (1.0f + __expf(-s));
    }
}

// ---------------------------------------------------------------------------
extern "C" void kernel_launch(void* const* d_in, const int* in_sizes, int n_in,
                              void* d_out, int out_size) {
    const int*   tokens = (const int*)  d_in[0];
    const float* emb    = (const float*)d_in[1];
    const float* W1     = (const float*)d_in[2];
    const float* U1     = (const float*)d_in[3];
    const float* b1     = (const float*)d_in[4];
    const float* W2     = (const float*)d_in[5];
    const float* U2     = (const float*)d_in[6];
    const float* b2     = (const float*)d_in[7];
    const float* Wout   = (const float*)d_in[8];
    const float* bout   = (const float*)d_in[9];

    build_tab<<<VOCAB, G3>>>(emb, W1, b1);
    gru_fused<<<BATCH, NTHR>>>(tokens, U1, b1, W2, U2, b2, Wout, bout,
                               (float*)d_out);
}

// round 16
// speedup vs baseline: 2.0588x; 1.2652x over previous
#include <cuda_runtime.h>
#include <cstdint>

#define T_LEN 4995
#define VOCAB 4096
#define EDIM  100
#define UDIM  64
#define G3    192    // 3*U gate width
#define GPAD  256    // padded gate row: [64 cols][4] (z,r,h,pad)
#define NTHR  256
#define KSLOT 1251   // slots of 4 timesteps
#define UMAX  1248   // last h1 bulk-copy index

// Precomputed (emb @ W1 + b1[0]) table, packed [VOCAB][64][4] = (z,r,h,0)
__device__ __align__(16) float g_tab[VOCAB * GPAD];

__device__ __forceinline__ void ffma2(float2& acc, const float2 a, const float2 b) {
    asm("fma.rn.f32x2 %0, %1, %2, %0;"
        : "+l"(reinterpret_cast<unsigned long long&>(acc))
        : "l"(*reinterpret_cast<const unsigned long long*>(&a)),
          "l"(*reinterpret_cast<const unsigned long long*>(&b)));
}
__device__ __forceinline__ float2 fadd2(const float2 a, const float2 b) {
    float2 r;
    asm("add.rn.f32x2 %0, %1, %2;"
        : "=l"(reinterpret_cast<unsigned long long&>(r))
        : "l"(*reinterpret_cast<const unsigned long long*>(&a)),
          "l"(*reinterpret_cast<const unsigned long long*>(&b)));
    return r;
}
__device__ __forceinline__ float tanha(float x) {
    float y; asm("tanh.approx.f32 %0, %1;" : "=f"(y) : "f"(x)); return y;
}
__device__ __forceinline__ float sigf(float x) {
    return fmaf(tanha(0.5f * x), 0.5f, 0.5f);
}
__device__ __forceinline__ uint32_t smem_u32(const void* p) {
    return (uint32_t)__cvta_generic_to_shared(p);
}
__device__ __forceinline__ uint32_t mapa1(uint32_t addr, uint32_t rank) {
    uint32_t r;
    asm("mapa.shared::cluster.u32 %0, %1, %2;" : "=r"(r) : "r"(addr), "r"(rank));
    return r;
}
__device__ __forceinline__ void mbar_wait(uint32_t mbar, uint32_t phase) {
    asm volatile(
        "{\n\t.reg .pred P;\n\t"
        "LW_%=:\n\t"
        "mbarrier.try_wait.parity.acquire.cta.shared::cta.b64 P, [%0], %1, 0x989680;\n\t"
        "@P bra.uni LD_%=;\n\t"
        "bra.uni LW_%=;\n\t"
        "LD_%=:\n\t}"
        :: "r"(mbar), "r"(phase) : "memory");
}
#define CLUSTER_SYNC() do { \
    asm volatile("barrier.cluster.arrive.aligned;" ::: "memory"); \
    asm volatile("barrier.cluster.wait.aligned;" ::: "memory"); \
} while (0)

// Pair-split 3-gate dot: half-dot of 32 k-values x 3 gates + shfl.xor 1 combine.
__device__ __forceinline__ void dot3(const float4* __restrict__ hv4,
                                     const float2 w[3][16],
                                     float bz, float br, float bh,
                                     float& s0, float& s1, float& s2) {
    float2 h[16];
#pragma unroll
    for (int m = 0; m < 8; m++) {
        const float4 v = hv4[m];
        h[2 * m]     = make_float2(v.x, v.y);
        h[2 * m + 1] = make_float2(v.z, v.w);
    }
    float2 a0 = {bz, 0.f}, a1 = {0.f, 0.f};
    float2 r0 = {br, 0.f}, r1 = {0.f, 0.f};
    float2 c0 = {bh, 0.f}, c1 = {0.f, 0.f};
#pragma unroll
    for (int m = 0; m < 16; m += 2) {
        ffma2(a0, h[m], w[0][m]); ffma2(a1, h[m + 1], w[0][m + 1]);
        ffma2(r0, h[m], w[1][m]); ffma2(r1, h[m + 1], w[1][m + 1]);
        ffma2(c0, h[m], w[2][m]); ffma2(c1, h[m + 1], w[2][m + 1]);
    }
    const float2 sa = fadd2(a0, a1), sr = fadd2(r0, r1), sc = fadd2(c0, c1);
    s0 = sa.x + sa.y;  s1 = sr.x + sr.y;  s2 = sc.x + sc.y;
    s0 += __shfl_xor_sync(0xFFFFFFFFu, s0, 1);
    s1 += __shfl_xor_sync(0xFFFFFFFFu, s1, 1);
    s2 += __shfl_xor_sync(0xFFFFFFFFu, s2, 1);
}

// ---------------------------------------------------------------------------
// Kernel 1: g_tab packed (z,r,h,0) per column
// ---------------------------------------------------------------------------
__global__ void build_tab(const float* __restrict__ emb,
                          const float* __restrict__ W1,
                          const float* __restrict__ b1) {
    __shared__ float es[EDIM];
    const int v = blockIdx.x;
    const int j = threadIdx.x;          // 0..191
    for (int e = j; e < EDIM; e += G3) es[e] = emb[v * EDIM + e];
    __syncthreads();
    float s = b1[j];
#pragma unroll 4
    for (int e = 0; e < EDIM; e++) s += es[e] * __ldg(&W1[e * G3 + j]);
    const int col = j & 63, g = j >> 6;
    g_tab[v * GPAD + col * 4 + g] = s;
    if (j < 64) g_tab[v * GPAD + j * 4 + 3] = 0.0f;
}

// ---------------------------------------------------------------------------
// Kernel 2: 2-CTA cluster pipeline, 4 timesteps per slot.
//   rank0: role A (tid<128, layer 1, named bar 1) + prefetch/copy (tid>=128)
//          end of slot k-1 h1[4(k-1)..4k-1] -> bulk DSMEM copy to rank1 at top
//          of slot k (1KB, mbarrier complete_tx on rank1's full[(k-1)&1]).
//   rank1: role C (tid<128, x2 = h1x@W2) + role B (tid>=128, layer 2, bar 2)
// Rings: h1s/h1x/h2s/x2s mod 8, xtr mod 16. full/empty mbarrier ring depth 2.
// ---------------------------------------------------------------------------
__global__ void __launch_bounds__(NTHR, 1) __cluster_dims__(2, 1, 1)
gru_fused(const int*   __restrict__ tokens,
          const float* __restrict__ U1w,
          const float* __restrict__ b1,
          const float* __restrict__ W2w,
          const float* __restrict__ U2w,
          const float* __restrict__ b2,
          const float* __restrict__ Wout,
          const float* __restrict__ bout,
          float*       __restrict__ out) {
    __shared__ __align__(16) float h1s[8][UDIM];   // rank0: layer-1 state ring
    __shared__ __align__(16) float h1x[8][UDIM];   // rank1: received h1 ring
    __shared__ __align__(16) float h2s[8][UDIM];   // rank1: layer-2 state ring
    __shared__ __align__(16) float x2s[8][GPAD];   // rank1: x2 ring
    __shared__ __align__(16) float xtr[16][GPAD];  // rank0: xt ring
    __shared__ __align__(16) float red[UDIM];
    __shared__ __align__(8) unsigned long long mbars[4]; // 0,1: empty(rank0)  2,3: full(rank1)

    const int tid  = threadIdx.x;
    const int bidx = blockIdx.x >> 1;
    uint32_t rank; asm("mov.u32 %0, %%cluster_ctarank;" : "=r"(rank));
    const long long tokbase = (long long)bidx * T_LEN;

    if (tid == 0) {
        const int base = (rank == 0) ? 0 : 2;
        asm volatile("mbarrier.init.shared.b64 [%0], 1;" :: "r"(smem_u32(&mbars[base]))     : "memory");
        asm volatile("mbarrier.init.shared.b64 [%0], 1;" :: "r"(smem_u32(&mbars[base + 1])) : "memory");
    }
    if (rank == 0) {
        if (tid < UDIM) h1s[7][tid] = 0.0f;        // h1[-1]
        for (int i = tid; i < 12 * GPAD; i += NTHR) {  // xt for steps 0..11
            const int tp  = i >> 8;
            const int tok = __ldg(tokens + tokbase + tp);
            xtr[tp][i & 255] = g_tab[tok * GPAD + (i & 255)];
        }
    } else {
        if (tid < UDIM) h2s[7][tid] = 0.0f;        // h2[-1]
    }
    __syncthreads();
    CLUSTER_SYNC();

    const int t2   = tid & 127;
    const int col  = t2 >> 1;
    const int half = t2 & 1;

    // ---- per-thread register weights ----
    float2 w[3][16];
    float bias[3];
    {
        const float* Wm = (rank == 0) ? U1w : (tid < 128 ? W2w : U2w);
        const bool needw = (rank == 1) || (tid < 128);
        if (needw) {
#pragma unroll
            for (int g = 0; g < 3; g++)
#pragma unroll
                for (int m = 0; m < 16; m++) {
                    const int k = half * 32 + 2 * m;
                    w[g][m] = make_float2(Wm[k * G3 + g * 64 + col],
                                          Wm[(k + 1) * G3 + g * 64 + col]);
                }
#pragma unroll
            for (int g = 0; g < 3; g++) {
                float bv;
                if (rank == 0)      bv = b1[G3 + g * 64 + col];   // L1 recurrent
                else if (tid < 128) bv = b2[g * 64 + col];        // L2 input
                else                bv = b2[G3 + g * 64 + col];   // L2 recurrent
                bias[g] = (half == 0) ? bv : 0.0f;
            }
        }
    }

    if (rank == 0) {
        // =================== CTA rank 0: role A + prefetch/copy ===============
        for (int k = 0; k < KSLOT; k++) {
            if (tid < 128) {
#pragma unroll
                for (int sub = 0; sub < 4; sub++) {
                    const int s = 4 * k + sub;
                    if (s < T_LEN) {
                        const float4* hv4 = (const float4*)(h1s[(s - 1) & 7]) + half * 8;
                        const float4 xv = *((const float4*)&xtr[s & 15][col * 4]);
                        float az, ar, ah;
                        dot3(hv4, w, bias[0], bias[1], bias[2], az, ar, ah);
                        const float z  = sigf(xv.x + az);
                        const float r  = sigf(xv.y + ar);
                        const float hh = tanha(fmaf(r, ah, xv.z));
                        const float hold = h1s[(s - 1) & 7][col];
                        if (half == 0)
                            h1s[s & 7][col] = fmaf(z, hold - hh, hh);
                    }
                    if (sub < 3)
                        asm volatile("bar.sync 1, 128;" ::: "memory");
                }
            } else {
                // ---- h1 bulk copy of previous slot's half to rank1 ----
                if (tid == 128 && k >= 1 && k <= UMAX + 1) {
                    const int u = k - 1;                         // copy index
                    mbar_wait(smem_u32(&mbars[u & 1]), ((u >> 1) & 1) ^ 1);
                    asm volatile("fence.proxy.async.shared::cta;" ::: "memory");
                    const uint32_t src = smem_u32(&h1s[0][0]) + (u & 1) * 1024u;
                    const uint32_t dst = mapa1(smem_u32(&h1x[0][0]) + (u & 1) * 1024u, 1);
                    const uint32_t mb  = mapa1(smem_u32(&mbars[2 + (u & 1)]), 1);
                    asm volatile(
                        "cp.async.bulk.shared::cluster.shared::cta.mbarrier::complete_tx::bytes "
                        "[%0], [%1], %2, [%3];"
                        :: "r"(dst), "r"(src), "r"(1024u), "r"(mb) : "memory");
                    asm volatile("cp.async.bulk.commit_group;" ::: "memory");
                }
                // ---- xt prefetch for steps 4k+12..4k+15 (256 x 16B) ----
                const int tp2 = tid - 128;
#pragma unroll
                for (int cc = 0; cc < 2; cc++) {
                    const int c  = tp2 + cc * 128;
                    const int tp = 4 * k + 12 + (c >> 6);
                    if (tp < T_LEN) {
                        const int tok = __ldg(tokens + tokbase + tp);
                        const float* src = g_tab + tok * GPAD + (c & 63) * 4;
                        unsigned dsm = (unsigned)__cvta_generic_to_shared(
                            &xtr[tp & 15][(c & 63) * 4]);
                        asm volatile("cp.async.cg.shared.global [%0], [%1], 16;"
                                     :: "r"(dsm), "l"(src) : "memory");
                    }
                }
                asm volatile("cp.async.commit_group;" ::: "memory");
                asm volatile("cp.async.wait_group 2;" ::: "memory");
                if (tid == 128)
                    asm volatile("cp.async.bulk.wait_group.read 0;" ::: "memory");
            }
            __syncthreads();
        }
    } else {
        // =================== CTA rank 1: roles C + B ==========================
        for (int k = 0; k < KSLOT; k++) {
            if (tid < 128) {
                if (tid == 0) {
                    if (k >= 2 && (k - 2) <= UMAX) {   // consumed use k-2 last slot
                        const uint32_t ra = mapa1(smem_u32(&mbars[k & 1]), 0);
                        asm volatile("mbarrier.arrive.shared::cluster.b64 _, [%0];"
                                     :: "r"(ra) : "memory");
                    }
                    if (k <= UMAX) {                   // expect copy u=k (arrives next slot+)
                        asm volatile("mbarrier.arrive.expect_tx.shared.b64 _, [%0], %1;"
                                     :: "r"(smem_u32(&mbars[2 + (k & 1)])), "r"(1024u)
                                     : "memory");
                    }
                }
                if (k >= 1 && (k - 1) <= UMAX) {       // wait h1[4k-4..4k-1]
                    const int u = k - 1;
                    mbar_wait(smem_u32(&mbars[2 + (u & 1)]), (u >> 1) & 1);
                }
                // ---- x2[4k-4 .. 4k-1]: independent dots on h1x ----
#pragma unroll
                for (int sub = 0; sub < 4; sub++) {
                    const int s = 4 * k - 4 + sub;
                    if (s >= 0 && s < T_LEN) {
                        const float4* hv4 = (const float4*)(h1x[s & 7]) + half * 8;
                        float sz, sr, sh;
                        dot3(hv4, w, bias[0], bias[1], bias[2], sz, sr, sh);
                        if (half == 0) {
                            float4* dst = (float4*)&x2s[s & 7][col * 4];
                            *dst = make_float4(sz, sr, sh, 0.0f);
                        }
                    }
                }
            } else {
                // ---- layer 2: steps 4k-8 .. 4k-5 ----
#pragma unroll
                for (int sub = 0; sub < 4; sub++) {
                    const int s = 4 * k - 8 + sub;
                    if (s >= 0 && s < T_LEN) {
                        const float4* hv4 = (const float4*)(h2s[(s - 1) & 7]) + half * 8;
                        const float4 xv = *((const float4*)&x2s[s & 7][col * 4]);
                        float az, ar, ah;
                        dot3(hv4, w, bias[0], bias[1], bias[2], az, ar, ah);
                        const float z  = sigf(xv.x + az);
                        const float r  = sigf(xv.y + ar);
                        const float hh = tanha(fmaf(r, ah, xv.z));
                        const float hold = h2s[(s - 1) & 7][col];
                        if (half == 0)
                            h2s[s & 7][col] = fmaf(z, hold - hh, hh);
                    }
                    if (sub < 3)
                        asm volatile("bar.sync 2, 128;" ::: "memory");
                }
            }
            __syncthreads();
        }
        // -------- Epilogue: sigmoid(h2[T-1] @ Wout + bout) --------
        if (tid < UDIM) red[tid] = h2s[(T_LEN - 1) & 7][tid] * Wout[tid];
        __syncthreads();
        if (tid == 0) {
            float s = bout[0];
#pragma unroll
            for (int q = 0; q < UDIM; q++) s += red[q];
            out[bidx] = 1.0f / (1.0f + __expf(-s));
        }
    }

    CLUSTER_SYNC();   // keep peer smem/barriers alive until both CTAs finish
}

// ---------------------------------------------------------------------------
extern "C" void kernel_launch(void* const* d_in, const int* in_sizes, int n_in,
                              void* d_out, int out_size) {
    const int*   tokens = (const int*)  d_in[0];
    const float* emb    = (const float*)d_in[1];
    const float* W1     = (const float*)d_in[2];
    const float* U1     = (const float*)d_in[3];
    const float* b1     = (const float*)d_in[4];
    const float* W2     = (const float*)d_in[5];
    const float* U2     = (const float*)d_in[6];
    const float* b2     = (const float*)d_in[7];
    const float* Wout   = (const float*)d_in[8];
    const float* bout   = (const float*)d_in[9];

    build_tab<<<VOCAB, G3>>>(emb, W1, b1);
    gru_fused<<<64 * 2, NTHR>>>(tokens, U1, b1, W2, U2, b2, Wout, bout,
                                (float*)d_out);
}